// round 14
// baseline (speedup 1.0000x reference)
#include <cuda_runtime.h>

#define CH 256
#define QEPS 1e-4f
#define RBLOCKS 444   // 3 per SM * 148
#define ABLOCKS 444

// Packed dual-FP32 ops (Blackwell FFMA2 — only reachable via PTX f32x2).
#define PACK2F(d, lo, hi) asm("mov.b64 %0, {%1, %2};" : "=l"(d) : "f"(lo), "f"(hi))
#define UNPACK2F(lo, hi, s) asm("mov.b64 {%0, %1}, %2;" : "=f"(lo), "=f"(hi) : "l"(s))
#define ADD2(acc, p)    asm("add.rn.f32x2 %0, %0, %1;" : "+l"(acc) : "l"(p))
#define FMA2(acc, p, q) asm("fma.rn.f32x2 %0, %1, %2, %0;" : "+l"(acc) : "l"(p), "l"(q))

// Scratch (no allocations allowed). Zero-initialized at module load; the
// stats tail of k_reduce re-zeroes g_sums/g_count after consuming them, so
// every graph replay sees a clean slate.
__device__ float g_sums[14 * CH];
__device__ float g_M[16 * CH];
__device__ float g_bias[4 * CH];   // beta - M @ mu  (folded bias)
__device__ unsigned g_count;

// ---------------------------------------------------------------------------
// Kernel 1: per-channel sums/product-sums + (last block) stats.
// thread: channel QUAD g = t&63, row phase rq = t>>6 (4 rows per step).
// float4 loads: 4 x LDG.128 = 64 B in flight per thread (matches k_apply's
// winning outstanding-bytes budget; float2 gave only 32 B -> 69.8% DRAM).
// FFMA2 packed accumulation: 28 packed ops per iteration (each float4 = 2
// packed f32x2 pairs) keeps issue + register pressure inside occ-3 budget.
// Chunked traversal (measured best). Block-reduce to g_sums via atomics;
// LAST block computes whitening, M = G @ W, folded bias, resets scratch.
// ---------------------------------------------------------------------------
__global__ void __launch_bounds__(256, 3) k_reduce(const float* __restrict__ x,
                                                   const float* __restrict__ gamma,
                                                   const float* __restrict__ beta,
                                                   int S, int rowsPerBlock) {
    const int t = threadIdx.x;
    const int g = t & 63;    // channel quad (c = 4g..4g+3)
    const int rq = t >> 6;   // row phase (0..3)

    int s0 = blockIdx.x * rowsPerBlock;
    int send = s0 + rowsPerBlock;
    if (send > S) send = S;

    const unsigned CS = (unsigned)S * CH;
    const unsigned gg = (unsigned)g * 4u;

    // acc[i][0] = packed (x,y), acc[i][1] = packed (z,w) of stat i
    unsigned long long acc[14][2];
#pragma unroll
    for (int i = 0; i < 14; ++i) { acc[i][0] = 0ull; acc[i][1] = 0ull; }

#pragma unroll 2
    for (int s = s0 + rq; s < send; s += 4) {
        unsigned base = (unsigned)s * CH + gg;
        float4 x0 = __ldcs((const float4*)(x + base));
        float4 x1 = __ldcs((const float4*)(x + CS + base));
        float4 x2 = __ldcs((const float4*)(x + 2 * CS + base));
        float4 x3 = __ldcs((const float4*)(x + 3 * CS + base));

        unsigned long long X0l, X0h, X1l, X1h, X2l, X2h, X3l, X3h;
        PACK2F(X0l, x0.x, x0.y); PACK2F(X0h, x0.z, x0.w);
        PACK2F(X1l, x1.x, x1.y); PACK2F(X1h, x1.z, x1.w);
        PACK2F(X2l, x2.x, x2.y); PACK2F(X2h, x2.z, x2.w);
        PACK2F(X3l, x3.x, x3.y); PACK2F(X3h, x3.z, x3.w);

        ADD2(acc[0][0], X0l);      ADD2(acc[0][1], X0h);
        ADD2(acc[1][0], X1l);      ADD2(acc[1][1], X1h);
        ADD2(acc[2][0], X2l);      ADD2(acc[2][1], X2h);
        ADD2(acc[3][0], X3l);      ADD2(acc[3][1], X3h);
        FMA2(acc[4][0], X0l, X0l); FMA2(acc[4][1], X0h, X0h);   // rr
        FMA2(acc[5][0], X0l, X1l); FMA2(acc[5][1], X0h, X1h);   // ri
        FMA2(acc[6][0], X0l, X2l); FMA2(acc[6][1], X0h, X2h);   // rj
        FMA2(acc[7][0], X0l, X3l); FMA2(acc[7][1], X0h, X3h);   // rk
        FMA2(acc[8][0], X1l, X1l); FMA2(acc[8][1], X1h, X1h);   // ii
        FMA2(acc[9][0], X1l, X2l); FMA2(acc[9][1], X1h, X2h);   // ij
        FMA2(acc[10][0], X1l, X3l); FMA2(acc[10][1], X1h, X3h); // ik
        FMA2(acc[11][0], X2l, X2l); FMA2(acc[11][1], X2h, X2h); // jj
        FMA2(acc[12][0], X2l, X3l); FMA2(acc[12][1], X2h, X3h); // jk
        FMA2(acc[13][0], X3l, X3l); FMA2(acc[13][1], X3h, X3h); // kk
    }

    float4 a[14];
#pragma unroll
    for (int i = 0; i < 14; ++i) {
        UNPACK2F(a[i].x, a[i].y, acc[i][0]);
        UNPACK2F(a[i].z, a[i].w, acc[i][1]);
    }

    __shared__ float4 red[512];   // 8 KB; two stats staged per pass
#pragma unroll
    for (int i = 0; i < 14; i += 2) {
        red[t] = a[i];
        red[256 + t] = a[i + 1];
        __syncthreads();
        if (t < 64) {
            float4 v = red[t], v1 = red[t + 64], v2 = red[t + 128], v3 = red[t + 192];
            v.x += v1.x + v2.x + v3.x;
            v.y += v1.y + v2.y + v3.y;
            v.z += v1.z + v2.z + v3.z;
            v.w += v1.w + v2.w + v3.w;
            float* dst = &g_sums[i * CH + t * 4];
            atomicAdd(dst + 0, v.x);
            atomicAdd(dst + 1, v.y);
            atomicAdd(dst + 2, v.z);
            atomicAdd(dst + 3, v.w);

            v = red[256 + t]; v1 = red[256 + t + 64];
            v2 = red[256 + t + 128]; v3 = red[256 + t + 192];
            v.x += v1.x + v2.x + v3.x;
            v.y += v1.y + v2.y + v3.y;
            v.z += v1.z + v2.z + v3.z;
            v.w += v1.w + v2.w + v3.w;
            dst = &g_sums[(i + 1) * CH + t * 4];
            atomicAdd(dst + 0, v.x);
            atomicAdd(dst + 1, v.y);
            atomicAdd(dst + 2, v.z);
            atomicAdd(dst + 3, v.w);
        }
        __syncthreads();
    }

    // ---- last-block stats tail (replaces a separate k_stats launch) ----
    __shared__ bool isLast;
    __threadfence();
    if (t == 0) {
        unsigned prev = atomicAdd(&g_count, 1u);
        isLast = (prev == (unsigned)gridDim.x - 1u);
    }
    __syncthreads();
    if (!isLast) return;

    if (t == 0) g_count = 0;   // reset for next graph replay

    const int c = t;           // thread = channel
    const float invN = 1.0f / (float)S;

    float mu[4];
#pragma unroll
    for (int p = 0; p < 4; ++p) mu[p] = __ldcg(&g_sums[p * CH + c]) * invN;

    // cov entries: 0 rr,1 ri,2 rj,3 rk,4 ii,5 ij,6 ik,7 jj,8 jk,9 kk
    const int ta[10] = {0, 0, 0, 0, 1, 1, 1, 2, 2, 3};
    const int tb[10] = {0, 1, 2, 3, 1, 2, 3, 2, 3, 3};
    float v[10];
#pragma unroll
    for (int i = 0; i < 10; ++i) {
        v[i] = __ldcg(&g_sums[(4 + i) * CH + c]) * invN - mu[ta[i]] * mu[tb[i]];
        if (ta[i] == tb[i]) v[i] += QEPS;
    }

    // consumed g_sums for this channel -> zero it for the next replay
#pragma unroll
    for (int i = 0; i < 14; ++i) g_sums[i * CH + c] = 0.0f;

    float wrr = sqrtf(v[0]);
    float wri = v[1] / wrr;
    float wii = sqrtf(v[4] - wri * wri);
    float wrj = v[2] / wrr;
    float wij = (v[5] - wri * wrj) / wii;
    float wjj = sqrtf(v[7] - (wij * wij + wrj * wrj));
    float wrk = v[3] / wrr;
    float wik = (v[6] - wri * wrk) / wii;
    float wjk = (v[8] - (wij * wik + wrj * wrk)) / wjj;
    float wkk = sqrtf(v[9] - (wjk * wjk + wik * wik + wrk * wrk));

    float orr = 1.0f / wrr, oii = 1.0f / wii, ojj = 1.0f / wjj, okk = 1.0f / wkk;
    float ori = -(wri * orr) / wii;
    float orj = -(wrj * orr + wij * ori) / wjj;
    float ork = -(wrk * orr + wik * ori + wjk * orj) / wkk;
    float oij = -(wij * oii) / wjj;
    float oik = -(wik * oii + wjk * oij) / wkk;
    float ojk = -(wjk * ojj) / wkk;

    float W[4][4] = {{orr, ori, orj, ork},
                     {ori, oii, oij, oik},
                     {orj, oij, ojj, ojk},
                     {ork, oik, ojk, okk}};

    float g0 = gamma[0 * CH + c], g1 = gamma[1 * CH + c], g2 = gamma[2 * CH + c];
    float g3 = gamma[3 * CH + c], g4 = gamma[4 * CH + c], g5 = gamma[5 * CH + c];
    float g6 = gamma[6 * CH + c], g7 = gamma[7 * CH + c], g8 = gamma[8 * CH + c];
    float g9 = gamma[9 * CH + c];
    float G[4][4] = {{g0, g1, g2, g3},
                     {g1, g4, g5, g6},
                     {g2, g5, g7, g8},
                     {g3, g6, g8, g9}};

#pragma unroll
    for (int p = 0; p < 4; ++p) {
        float bias = beta[p * CH + c];
#pragma unroll
        for (int s = 0; s < 4; ++s) {
            float acc2 = 0.f;
#pragma unroll
            for (int q = 0; q < 4; ++q) acc2 += G[p][q] * W[q][s];
            g_M[(p * 4 + s) * CH + c] = acc2;
            bias -= acc2 * mu[s];   // fold mean: bias' = beta - M @ mu
        }
        g_bias[p * CH + c] = bias;
    }
}

// ---------------------------------------------------------------------------
// Kernel 2: out[p] = sum_q M[p][q] * x[q] + bias'[p].
// float2 over channels, M + bias register-resident, 2 spatial rows per
// iteration (8 outstanding LDG.64 per thread). Persistent grid-stride,
// streaming cache hints (zero reuse). launch_bounds(256,3) -> 24 warps/SM.
// ---------------------------------------------------------------------------
__global__ void __launch_bounds__(256, 3) k_apply(const float* __restrict__ x,
                                                  float* __restrict__ out, int S) {
    const int t = threadIdx.x;
    const int g = t & 127;   // channel pair index
    const int rq = t >> 7;   // row phase (0..1)

    const float2* M2 = (const float2*)g_M;
    const float2* B2 = (const float2*)g_bias;

    float2 m[16], b[4];
#pragma unroll
    for (int i = 0; i < 16; ++i) m[i] = M2[i * 128 + g];
#pragma unroll
    for (int p = 0; p < 4; ++p) b[p] = B2[p * 128 + g];

    const unsigned CS = (unsigned)S * CH;
    const unsigned stride = (unsigned)gridDim.x * 4u;   // 4 rows per block-iter
    const unsigned Sv = (unsigned)S & ~3u;              // multiple-of-4 body

    unsigned s = (unsigned)blockIdx.x * 4u + rq;
    for (; s + 2 < Sv; s += stride) {
        unsigned bA = s * CH + (unsigned)g * 2u;
        unsigned bB = bA + 2u * CH;                     // row s+2
        float2 xA0 = __ldcs((const float2*)(x + bA));
        float2 xB0 = __ldcs((const float2*)(x + bB));
        float2 xA1 = __ldcs((const float2*)(x + CS + bA));
        float2 xB1 = __ldcs((const float2*)(x + CS + bB));
        float2 xA2 = __ldcs((const float2*)(x + 2 * CS + bA));
        float2 xB2 = __ldcs((const float2*)(x + 2 * CS + bB));
        float2 xA3 = __ldcs((const float2*)(x + 3 * CS + bA));
        float2 xB3 = __ldcs((const float2*)(x + 3 * CS + bB));
#pragma unroll
        for (int p = 0; p < 4; ++p) {
            float2 oA = b[p], oB = b[p];
            oA.x += m[p * 4 + 0].x * xA0.x; oA.y += m[p * 4 + 0].y * xA0.y;
            oB.x += m[p * 4 + 0].x * xB0.x; oB.y += m[p * 4 + 0].y * xB0.y;
            oA.x += m[p * 4 + 1].x * xA1.x; oA.y += m[p * 4 + 1].y * xA1.y;
            oB.x += m[p * 4 + 1].x * xB1.x; oB.y += m[p * 4 + 1].y * xB1.y;
            oA.x += m[p * 4 + 2].x * xA2.x; oA.y += m[p * 4 + 2].y * xA2.y;
            oB.x += m[p * 4 + 2].x * xB2.x; oB.y += m[p * 4 + 2].y * xB2.y;
            oA.x += m[p * 4 + 3].x * xA3.x; oA.y += m[p * 4 + 3].y * xA3.y;
            oB.x += m[p * 4 + 3].x * xB3.x; oB.y += m[p * 4 + 3].y * xB3.y;
            __stcs((float2*)(out + p * CS + bA), oA);
            __stcs((float2*)(out + p * CS + bB), oB);
        }
    }
    // tail (also covers the residual rows when S % 4 != 0)
    for (; s < (unsigned)S; s += 2u) {
        unsigned base = s * CH + (unsigned)g * 2u;
        float2 x0 = __ldcs((const float2*)(x + base));
        float2 x1 = __ldcs((const float2*)(x + CS + base));
        float2 x2 = __ldcs((const float2*)(x + 2 * CS + base));
        float2 x3 = __ldcs((const float2*)(x + 3 * CS + base));
#pragma unroll
        for (int p = 0; p < 4; ++p) {
            float2 o = b[p];
            o.x += m[p * 4 + 0].x * x0.x; o.y += m[p * 4 + 0].y * x0.y;
            o.x += m[p * 4 + 1].x * x1.x; o.y += m[p * 4 + 1].y * x1.y;
            o.x += m[p * 4 + 2].x * x2.x; o.y += m[p * 4 + 2].y * x2.y;
            o.x += m[p * 4 + 3].x * x3.x; o.y += m[p * 4 + 3].y * x3.y;
            __stcs((float2*)(out + p * CS + base), o);
        }
    }
}

// ---------------------------------------------------------------------------
extern "C" void kernel_launch(void* const* d_in, const int* in_sizes, int n_in,
                              void* d_out, int out_size) {
    const float* x = (const float*)d_in[0];
    const float* gamma = (const float*)d_in[1];
    const float* beta = (const float*)d_in[2];
    float* out = (float*)d_out;

    const int S = in_sizes[0] / (4 * CH);  // spatial rows per component (B*H*W)
    const int rowsPerBlock = (S + RBLOCKS - 1) / RBLOCKS;

    k_reduce<<<RBLOCKS, 256>>>(x, gamma, beta, S, rowsPerBlock);
    k_apply<<<ABLOCKS, 256>>>(x, out, S);
}

// round 15
// speedup vs baseline: 1.0942x; 1.0942x over previous
#include <cuda_runtime.h>

#define CH 256
#define QEPS 1e-4f
#define RBLOCKS 444   // 3 per SM * 148
#define ABLOCKS 444

// Scratch (no allocations allowed). Zero-initialized at module load; k_stats
// re-zeroes g_sums after consuming it, so every graph replay sees zeros.
__device__ float g_sums[14 * CH];
__device__ float g_M[16 * CH];
__device__ float g_bias[4 * CH];   // beta - M @ mu  (folded bias)

// ---------------------------------------------------------------------------
// Kernel 1: per-channel sums and product-sums, float2 over channels.
// thread: channel pair g = t&127, row phase rq = t>>7 (2 rows per step).
// 14 float2 register accumulators; streaming loads; unroll 8 for MLP.
// (Measured-best structure: chunked traversal + simple loop; every
//  restructure — 8-load body, float4 lanes, grid-stride, occ-4 — regressed.)
// smem block-reduce over the 2 row-phase threads, then atomics.
// ---------------------------------------------------------------------------
__global__ void __launch_bounds__(256, 3) k_reduce(const float* __restrict__ x,
                                                   int S, int rowsPerBlock) {
    const int t = threadIdx.x;
    const int g = t & 127;
    const int rq = t >> 7;

    int s0 = blockIdx.x * rowsPerBlock;
    int send = s0 + rowsPerBlock;
    if (send > S) send = S;

    const unsigned CS = (unsigned)S * CH;

    float2 a[14];
#pragma unroll
    for (int i = 0; i < 14; ++i) a[i] = make_float2(0.f, 0.f);

#pragma unroll 8
    for (int s = s0 + rq; s < send; s += 2) {
        unsigned base = (unsigned)s * CH + (unsigned)g * 2u;
        float2 x0 = __ldcs((const float2*)(x + base));
        float2 x1 = __ldcs((const float2*)(x + CS + base));
        float2 x2 = __ldcs((const float2*)(x + 2 * CS + base));
        float2 x3 = __ldcs((const float2*)(x + 3 * CS + base));

        a[0].x += x0.x;        a[0].y += x0.y;
        a[1].x += x1.x;        a[1].y += x1.y;
        a[2].x += x2.x;        a[2].y += x2.y;
        a[3].x += x3.x;        a[3].y += x3.y;
        a[4].x += x0.x * x0.x; a[4].y += x0.y * x0.y;   // rr
        a[5].x += x0.x * x1.x; a[5].y += x0.y * x1.y;   // ri
        a[6].x += x0.x * x2.x; a[6].y += x0.y * x2.y;   // rj
        a[7].x += x0.x * x3.x; a[7].y += x0.y * x3.y;   // rk
        a[8].x += x1.x * x1.x; a[8].y += x1.y * x1.y;   // ii
        a[9].x += x1.x * x2.x; a[9].y += x1.y * x2.y;   // ij
        a[10].x += x1.x * x3.x; a[10].y += x1.y * x3.y; // ik
        a[11].x += x2.x * x2.x; a[11].y += x2.y * x2.y; // jj
        a[12].x += x2.x * x3.x; a[12].y += x2.y * x3.y; // jk
        a[13].x += x3.x * x3.x; a[13].y += x3.y * x3.y; // kk
    }

    __shared__ float2 red[512];
    // stage two accumulators per pass to halve the sync count
#pragma unroll
    for (int i = 0; i < 14; i += 2) {
        red[t] = a[i];
        red[256 + t] = a[i + 1];
        __syncthreads();
        if (t < 128) {
            float2 v = red[t], w = red[t + 128];
            v.x += w.x; v.y += w.y;
            float* dst = &g_sums[i * CH + t * 2];
            atomicAdd(dst + 0, v.x);
            atomicAdd(dst + 1, v.y);
            v = red[256 + t]; w = red[256 + t + 128];
            v.x += w.x; v.y += w.y;
            dst = &g_sums[(i + 1) * CH + t * 2];
            atomicAdd(dst + 0, v.x);
            atomicAdd(dst + 1, v.y);
        }
        __syncthreads();
    }
}

// ---------------------------------------------------------------------------
// Kernel 2: stats -> whitening -> M = G @ W, folded bias = beta - M @ mu.
// One block, thread = channel. Mirrors _whitening_matrix exactly.
// Afterwards zeroes g_sums so the next graph replay starts clean.
// ---------------------------------------------------------------------------
__global__ void k_stats(const float* __restrict__ gamma,
                        const float* __restrict__ beta, int S) {
    const int c = threadIdx.x;
    const float invN = 1.0f / (float)S;

    float mu[4];
#pragma unroll
    for (int p = 0; p < 4; ++p) mu[p] = g_sums[p * CH + c] * invN;

    // cov entries: 0 rr,1 ri,2 rj,3 rk,4 ii,5 ij,6 ik,7 jj,8 jk,9 kk
    const int ta[10] = {0, 0, 0, 0, 1, 1, 1, 2, 2, 3};
    const int tb[10] = {0, 1, 2, 3, 1, 2, 3, 2, 3, 3};
    float v[10];
#pragma unroll
    for (int i = 0; i < 10; ++i) {
        v[i] = g_sums[(4 + i) * CH + c] * invN - mu[ta[i]] * mu[tb[i]];
        if (ta[i] == tb[i]) v[i] += QEPS;
    }

    // consumed g_sums for this channel -> zero it for the next replay
#pragma unroll
    for (int i = 0; i < 14; ++i) g_sums[i * CH + c] = 0.0f;

    float wrr = sqrtf(v[0]);
    float wri = v[1] / wrr;
    float wii = sqrtf(v[4] - wri * wri);
    float wrj = v[2] / wrr;
    float wij = (v[5] - wri * wrj) / wii;
    float wjj = sqrtf(v[7] - (wij * wij + wrj * wrj));
    float wrk = v[3] / wrr;
    float wik = (v[6] - wri * wrk) / wii;
    float wjk = (v[8] - (wij * wik + wrj * wrk)) / wjj;
    float wkk = sqrtf(v[9] - (wjk * wjk + wik * wik + wrk * wrk));

    float orr = 1.0f / wrr, oii = 1.0f / wii, ojj = 1.0f / wjj, okk = 1.0f / wkk;
    float ori = -(wri * orr) / wii;
    float orj = -(wrj * orr + wij * ori) / wjj;
    float ork = -(wrk * orr + wik * ori + wjk * orj) / wkk;
    float oij = -(wij * oii) / wjj;
    float oik = -(wik * oii + wjk * oij) / wkk;
    float ojk = -(wjk * ojj) / wkk;

    float W[4][4] = {{orr, ori, orj, ork},
                     {ori, oii, oij, oik},
                     {orj, oij, ojj, ojk},
                     {ork, oik, ojk, okk}};

    float g0 = gamma[0 * CH + c], g1 = gamma[1 * CH + c], g2 = gamma[2 * CH + c];
    float g3 = gamma[3 * CH + c], g4 = gamma[4 * CH + c], g5 = gamma[5 * CH + c];
    float g6 = gamma[6 * CH + c], g7 = gamma[7 * CH + c], g8 = gamma[8 * CH + c];
    float g9 = gamma[9 * CH + c];
    float G[4][4] = {{g0, g1, g2, g3},
                     {g1, g4, g5, g6},
                     {g2, g5, g7, g8},
                     {g3, g6, g8, g9}};

#pragma unroll
    for (int p = 0; p < 4; ++p) {
        float bias = beta[p * CH + c];
#pragma unroll
        for (int s = 0; s < 4; ++s) {
            float acc = 0.f;
#pragma unroll
            for (int q = 0; q < 4; ++q) acc += G[p][q] * W[q][s];
            g_M[(p * 4 + s) * CH + c] = acc;
            bias -= acc * mu[s];   // fold mean: bias' = beta - M @ mu
        }
        g_bias[p * CH + c] = bias;
    }
}

// ---------------------------------------------------------------------------
// Kernel 3: out[p] = sum_q M[p][q] * x[q] + bias'[p].
// float2 over channels, M + bias register-resident, 2 spatial rows per
// iteration (8 outstanding LDG.64 per thread). Persistent grid-stride,
// streaming cache hints (zero reuse). launch_bounds(256,3) -> 24 warps/SM.
// ---------------------------------------------------------------------------
__global__ void __launch_bounds__(256, 3) k_apply(const float* __restrict__ x,
                                                  float* __restrict__ out, int S) {
    const int t = threadIdx.x;
    const int g = t & 127;   // channel pair index
    const int rq = t >> 7;   // row phase (0..1)

    const float2* M2 = (const float2*)g_M;
    const float2* B2 = (const float2*)g_bias;

    float2 m[16], b[4];
#pragma unroll
    for (int i = 0; i < 16; ++i) m[i] = M2[i * 128 + g];
#pragma unroll
    for (int p = 0; p < 4; ++p) b[p] = B2[p * 128 + g];

    const unsigned CS = (unsigned)S * CH;
    const unsigned stride = (unsigned)gridDim.x * 4u;   // 4 rows per block-iter
    const unsigned Sv = (unsigned)S & ~3u;              // multiple-of-4 body

    unsigned s = (unsigned)blockIdx.x * 4u + rq;
    for (; s + 2 < Sv; s += stride) {
        unsigned bA = s * CH + (unsigned)g * 2u;
        unsigned bB = bA + 2u * CH;                     // row s+2
        float2 xA0 = __ldcs((const float2*)(x + bA));
        float2 xB0 = __ldcs((const float2*)(x + bB));
        float2 xA1 = __ldcs((const float2*)(x + CS + bA));
        float2 xB1 = __ldcs((const float2*)(x + CS + bB));
        float2 xA2 = __ldcs((const float2*)(x + 2 * CS + bA));
        float2 xB2 = __ldcs((const float2*)(x + 2 * CS + bB));
        float2 xA3 = __ldcs((const float2*)(x + 3 * CS + bA));
        float2 xB3 = __ldcs((const float2*)(x + 3 * CS + bB));
#pragma unroll
        for (int p = 0; p < 4; ++p) {
            float2 oA = b[p], oB = b[p];
            oA.x += m[p * 4 + 0].x * xA0.x; oA.y += m[p * 4 + 0].y * xA0.y;
            oB.x += m[p * 4 + 0].x * xB0.x; oB.y += m[p * 4 + 0].y * xB0.y;
            oA.x += m[p * 4 + 1].x * xA1.x; oA.y += m[p * 4 + 1].y * xA1.y;
            oB.x += m[p * 4 + 1].x * xB1.x; oB.y += m[p * 4 + 1].y * xB1.y;
            oA.x += m[p * 4 + 2].x * xA2.x; oA.y += m[p * 4 + 2].y * xA2.y;
            oB.x += m[p * 4 + 2].x * xB2.x; oB.y += m[p * 4 + 2].y * xB2.y;
            oA.x += m[p * 4 + 3].x * xA3.x; oA.y += m[p * 4 + 3].y * xA3.y;
            oB.x += m[p * 4 + 3].x * xB3.x; oB.y += m[p * 4 + 3].y * xB3.y;
            __stcs((float2*)(out + p * CS + bA), oA);
            __stcs((float2*)(out + p * CS + bB), oB);
        }
    }
    // tail (also covers the residual rows when S % 4 != 0)
    for (; s < (unsigned)S; s += 2u) {
        unsigned base = s * CH + (unsigned)g * 2u;
        float2 x0 = __ldcs((const float2*)(x + base));
        float2 x1 = __ldcs((const float2*)(x + CS + base));
        float2 x2 = __ldcs((const float2*)(x + 2 * CS + base));
        float2 x3 = __ldcs((const float2*)(x + 3 * CS + base));
#pragma unroll
        for (int p = 0; p < 4; ++p) {
            float2 o = b[p];
            o.x += m[p * 4 + 0].x * x0.x; o.y += m[p * 4 + 0].y * x0.y;
            o.x += m[p * 4 + 1].x * x1.x; o.y += m[p * 4 + 1].y * x1.y;
            o.x += m[p * 4 + 2].x * x2.x; o.y += m[p * 4 + 2].y * x2.y;
            o.x += m[p * 4 + 3].x * x3.x; o.y += m[p * 4 + 3].y * x3.y;
            __stcs((float2*)(out + p * CS + base), o);
        }
    }
}

// ---------------------------------------------------------------------------
extern "C" void kernel_launch(void* const* d_in, const int* in_sizes, int n_in,
                              void* d_out, int out_size) {
    const float* x = (const float*)d_in[0];
    const float* gamma = (const float*)d_in[1];
    const float* beta = (const float*)d_in[2];
    float* out = (float*)d_out;

    const int S = in_sizes[0] / (4 * CH);  // spatial rows per component (B*H*W)
    const int rowsPerBlock = (S + RBLOCKS - 1) / RBLOCKS;

    k_reduce<<<RBLOCKS, 256>>>(x, S, rowsPerBlock);
    k_stats<<<1, CH>>>(gamma, beta, S);
    k_apply<<<ABLOCKS, 256>>>(x, out, S);
}

// round 16
// speedup vs baseline: 1.1007x; 1.0059x over previous
#include <cuda_runtime.h>

#define CH 256
#define QEPS 1e-4f
#define RBLOCKS 444   // 3 per SM * 148
#define ABLOCKS 444

// Scratch (no allocations allowed). Zero-initialized at module load; k_stats
// re-zeroes g_sums after consuming it, so every graph replay sees zeros.
__device__ float g_sums[14 * CH];
__device__ float g_M[16 * CH];
__device__ float g_bias[4 * CH];   // beta - M @ mu  (folded bias)

// ---------------------------------------------------------------------------
// Kernel 1: per-channel sums and product-sums, float2 over channels.
// thread: channel pair g = t&127, row phase rq = t>>7 (2 rows per step).
// SOFTWARE-PIPELINED: next iteration's 4 loads issue before the current
// iteration's 28 FMAs -> 8 loads in flight per thread WITHOUT the register
// blowup that made the explicit 8-load bodies spill (R5/R7/R10/R14).
// Peak regs ~60 (28 accum + 8 cur + 8 next + addressing) < 84 cap.
// smem block-reduce over the 2 row-phase threads, then atomics.
// ---------------------------------------------------------------------------
__global__ void __launch_bounds__(256, 3) k_reduce(const float* __restrict__ x,
                                                   int S, int rowsPerBlock) {
    const int t = threadIdx.x;
    const int g = t & 127;
    const int rq = t >> 7;

    int s0 = blockIdx.x * rowsPerBlock;
    int send = s0 + rowsPerBlock;
    if (send > S) send = S;

    const unsigned CS = (unsigned)S * CH;
    const unsigned gg = (unsigned)g * 2u;

    float2 a[14];
#pragma unroll
    for (int i = 0; i < 14; ++i) a[i] = make_float2(0.f, 0.f);

    int s = s0 + rq;
    if (s < send) {
        unsigned base = (unsigned)s * CH + gg;
        float2 c0 = __ldcs((const float2*)(x + base));
        float2 c1 = __ldcs((const float2*)(x + CS + base));
        float2 c2 = __ldcs((const float2*)(x + 2 * CS + base));
        float2 c3 = __ldcs((const float2*)(x + 3 * CS + base));

#pragma unroll 4
        for (int sn = s + 2; sn < send; sn += 2) {
            // prefetch next iteration's rows BEFORE consuming current
            unsigned nb = (unsigned)sn * CH + gg;
            float2 n0 = __ldcs((const float2*)(x + nb));
            float2 n1 = __ldcs((const float2*)(x + CS + nb));
            float2 n2 = __ldcs((const float2*)(x + 2 * CS + nb));
            float2 n3 = __ldcs((const float2*)(x + 3 * CS + nb));

            a[0].x += c0.x;        a[0].y += c0.y;
            a[1].x += c1.x;        a[1].y += c1.y;
            a[2].x += c2.x;        a[2].y += c2.y;
            a[3].x += c3.x;        a[3].y += c3.y;
            a[4].x += c0.x * c0.x; a[4].y += c0.y * c0.y;   // rr
            a[5].x += c0.x * c1.x; a[5].y += c0.y * c1.y;   // ri
            a[6].x += c0.x * c2.x; a[6].y += c0.y * c2.y;   // rj
            a[7].x += c0.x * c3.x; a[7].y += c0.y * c3.y;   // rk
            a[8].x += c1.x * c1.x; a[8].y += c1.y * c1.y;   // ii
            a[9].x += c1.x * c2.x; a[9].y += c1.y * c2.y;   // ij
            a[10].x += c1.x * c3.x; a[10].y += c1.y * c3.y; // ik
            a[11].x += c2.x * c2.x; a[11].y += c2.y * c2.y; // jj
            a[12].x += c2.x * c3.x; a[12].y += c2.y * c3.y; // jk
            a[13].x += c3.x * c3.x; a[13].y += c3.y * c3.y; // kk

            c0 = n0; c1 = n1; c2 = n2; c3 = n3;
        }

        // epilogue: consume the last loaded rows
        a[0].x += c0.x;        a[0].y += c0.y;
        a[1].x += c1.x;        a[1].y += c1.y;
        a[2].x += c2.x;        a[2].y += c2.y;
        a[3].x += c3.x;        a[3].y += c3.y;
        a[4].x += c0.x * c0.x; a[4].y += c0.y * c0.y;
        a[5].x += c0.x * c1.x; a[5].y += c0.y * c1.y;
        a[6].x += c0.x * c2.x; a[6].y += c0.y * c2.y;
        a[7].x += c0.x * c3.x; a[7].y += c0.y * c3.y;
        a[8].x += c1.x * c1.x; a[8].y += c1.y * c1.y;
        a[9].x += c1.x * c2.x; a[9].y += c1.y * c2.y;
        a[10].x += c1.x * c3.x; a[10].y += c1.y * c3.y;
        a[11].x += c2.x * c2.x; a[11].y += c2.y * c2.y;
        a[12].x += c2.x * c3.x; a[12].y += c2.y * c3.y;
        a[13].x += c3.x * c3.x; a[13].y += c3.y * c3.y;
    }

    __shared__ float2 red[512];
    // stage two accumulators per pass to halve the sync count
#pragma unroll
    for (int i = 0; i < 14; i += 2) {
        red[t] = a[i];
        red[256 + t] = a[i + 1];
        __syncthreads();
        if (t < 128) {
            float2 v = red[t], w = red[t + 128];
            v.x += w.x; v.y += w.y;
            float* dst = &g_sums[i * CH + t * 2];
            atomicAdd(dst + 0, v.x);
            atomicAdd(dst + 1, v.y);
            v = red[256 + t]; w = red[256 + t + 128];
            v.x += w.x; v.y += w.y;
            dst = &g_sums[(i + 1) * CH + t * 2];
            atomicAdd(dst + 0, v.x);
            atomicAdd(dst + 1, v.y);
        }
        __syncthreads();
    }
}

// ---------------------------------------------------------------------------
// Kernel 2: stats -> whitening -> M = G @ W, folded bias = beta - M @ mu.
// One block, thread = channel. Mirrors _whitening_matrix exactly.
// Afterwards zeroes g_sums so the next graph replay starts clean.
// ---------------------------------------------------------------------------
__global__ void k_stats(const float* __restrict__ gamma,
                        const float* __restrict__ beta, int S) {
    const int c = threadIdx.x;
    const float invN = 1.0f / (float)S;

    float mu[4];
#pragma unroll
    for (int p = 0; p < 4; ++p) mu[p] = g_sums[p * CH + c] * invN;

    // cov entries: 0 rr,1 ri,2 rj,3 rk,4 ii,5 ij,6 ik,7 jj,8 jk,9 kk
    const int ta[10] = {0, 0, 0, 0, 1, 1, 1, 2, 2, 3};
    const int tb[10] = {0, 1, 2, 3, 1, 2, 3, 2, 3, 3};
    float v[10];
#pragma unroll
    for (int i = 0; i < 10; ++i) {
        v[i] = g_sums[(4 + i) * CH + c] * invN - mu[ta[i]] * mu[tb[i]];
        if (ta[i] == tb[i]) v[i] += QEPS;
    }

    // consumed g_sums for this channel -> zero it for the next replay
#pragma unroll
    for (int i = 0; i < 14; ++i) g_sums[i * CH + c] = 0.0f;

    float wrr = sqrtf(v[0]);
    float wri = v[1] / wrr;
    float wii = sqrtf(v[4] - wri * wri);
    float wrj = v[2] / wrr;
    float wij = (v[5] - wri * wrj) / wii;
    float wjj = sqrtf(v[7] - (wij * wij + wrj * wrj));
    float wrk = v[3] / wrr;
    float wik = (v[6] - wri * wrk) / wii;
    float wjk = (v[8] - (wij * wik + wrj * wrk)) / wjj;
    float wkk = sqrtf(v[9] - (wjk * wjk + wik * wik + wrk * wrk));

    float orr = 1.0f / wrr, oii = 1.0f / wii, ojj = 1.0f / wjj, okk = 1.0f / wkk;
    float ori = -(wri * orr) / wii;
    float orj = -(wrj * orr + wij * ori) / wjj;
    float ork = -(wrk * orr + wik * ori + wjk * orj) / wkk;
    float oij = -(wij * oii) / wjj;
    float oik = -(wik * oii + wjk * oij) / wkk;
    float ojk = -(wjk * ojj) / wkk;

    float W[4][4] = {{orr, ori, orj, ork},
                     {ori, oii, oij, oik},
                     {orj, oij, ojj, ojk},
                     {ork, oik, ojk, okk}};

    float g0 = gamma[0 * CH + c], g1 = gamma[1 * CH + c], g2 = gamma[2 * CH + c];
    float g3 = gamma[3 * CH + c], g4 = gamma[4 * CH + c], g5 = gamma[5 * CH + c];
    float g6 = gamma[6 * CH + c], g7 = gamma[7 * CH + c], g8 = gamma[8 * CH + c];
    float g9 = gamma[9 * CH + c];
    float G[4][4] = {{g0, g1, g2, g3},
                     {g1, g4, g5, g6},
                     {g2, g5, g7, g8},
                     {g3, g6, g8, g9}};

#pragma unroll
    for (int p = 0; p < 4; ++p) {
        float bias = beta[p * CH + c];
#pragma unroll
        for (int s = 0; s < 4; ++s) {
            float acc = 0.f;
#pragma unroll
            for (int q = 0; q < 4; ++q) acc += G[p][q] * W[q][s];
            g_M[(p * 4 + s) * CH + c] = acc;
            bias -= acc * mu[s];   // fold mean: bias' = beta - M @ mu
        }
        g_bias[p * CH + c] = bias;
    }
}

// ---------------------------------------------------------------------------
// Kernel 3: out[p] = sum_q M[p][q] * x[q] + bias'[p].
// float2 over channels, M + bias register-resident, 2 spatial rows per
// iteration (8 outstanding LDG.64 per thread). Persistent grid-stride,
// streaming cache hints (zero reuse). launch_bounds(256,3) -> 24 warps/SM.
// ---------------------------------------------------------------------------
__global__ void __launch_bounds__(256, 3) k_apply(const float* __restrict__ x,
                                                  float* __restrict__ out, int S) {
    const int t = threadIdx.x;
    const int g = t & 127;   // channel pair index
    const int rq = t >> 7;   // row phase (0..1)

    const float2* M2 = (const float2*)g_M;
    const float2* B2 = (const float2*)g_bias;

    float2 m[16], b[4];
#pragma unroll
    for (int i = 0; i < 16; ++i) m[i] = M2[i * 128 + g];
#pragma unroll
    for (int p = 0; p < 4; ++p) b[p] = B2[p * 128 + g];

    const unsigned CS = (unsigned)S * CH;
    const unsigned stride = (unsigned)gridDim.x * 4u;   // 4 rows per block-iter
    const unsigned Sv = (unsigned)S & ~3u;              // multiple-of-4 body

    unsigned s = (unsigned)blockIdx.x * 4u + rq;
    for (; s + 2 < Sv; s += stride) {
        unsigned bA = s * CH + (unsigned)g * 2u;
        unsigned bB = bA + 2u * CH;                     // row s+2
        float2 xA0 = __ldcs((const float2*)(x + bA));
        float2 xB0 = __ldcs((const float2*)(x + bB));
        float2 xA1 = __ldcs((const float2*)(x + CS + bA));
        float2 xB1 = __ldcs((const float2*)(x + CS + bB));
        float2 xA2 = __ldcs((const float2*)(x + 2 * CS + bA));
        float2 xB2 = __ldcs((const float2*)(x + 2 * CS + bB));
        float2 xA3 = __ldcs((const float2*)(x + 3 * CS + bA));
        float2 xB3 = __ldcs((const float2*)(x + 3 * CS + bB));
#pragma unroll
        for (int p = 0; p < 4; ++p) {
            float2 oA = b[p], oB = b[p];
            oA.x += m[p * 4 + 0].x * xA0.x; oA.y += m[p * 4 + 0].y * xA0.y;
            oB.x += m[p * 4 + 0].x * xB0.x; oB.y += m[p * 4 + 0].y * xB0.y;
            oA.x += m[p * 4 + 1].x * xA1.x; oA.y += m[p * 4 + 1].y * xA1.y;
            oB.x += m[p * 4 + 1].x * xB1.x; oB.y += m[p * 4 + 1].y * xB1.y;
            oA.x += m[p * 4 + 2].x * xA2.x; oA.y += m[p * 4 + 2].y * xA2.y;
            oB.x += m[p * 4 + 2].x * xB2.x; oB.y += m[p * 4 + 2].y * xB2.y;
            oA.x += m[p * 4 + 3].x * xA3.x; oA.y += m[p * 4 + 3].y * xA3.y;
            oB.x += m[p * 4 + 3].x * xB3.x; oB.y += m[p * 4 + 3].y * xB3.y;
            __stcs((float2*)(out + p * CS + bA), oA);
            __stcs((float2*)(out + p * CS + bB), oB);
        }
    }
    // tail (also covers the residual rows when S % 4 != 0)
    for (; s < (unsigned)S; s += 2u) {
        unsigned base = s * CH + (unsigned)g * 2u;
        float2 x0 = __ldcs((const float2*)(x + base));
        float2 x1 = __ldcs((const float2*)(x + CS + base));
        float2 x2 = __ldcs((const float2*)(x + 2 * CS + base));
        float2 x3 = __ldcs((const float2*)(x + 3 * CS + base));
#pragma unroll
        for (int p = 0; p < 4; ++p) {
            float2 o = b[p];
            o.x += m[p * 4 + 0].x * x0.x; o.y += m[p * 4 + 0].y * x0.y;
            o.x += m[p * 4 + 1].x * x1.x; o.y += m[p * 4 + 1].y * x1.y;
            o.x += m[p * 4 + 2].x * x2.x; o.y += m[p * 4 + 2].y * x2.y;
            o.x += m[p * 4 + 3].x * x3.x; o.y += m[p * 4 + 3].y * x3.y;
            __stcs((float2*)(out + p * CS + base), o);
        }
    }
}

// ---------------------------------------------------------------------------
extern "C" void kernel_launch(void* const* d_in, const int* in_sizes, int n_in,
                              void* d_out, int out_size) {
    const float* x = (const float*)d_in[0];
    const float* gamma = (const float*)d_in[1];
    const float* beta = (const float*)d_in[2];
    float* out = (float*)d_out;

    const int S = in_sizes[0] / (4 * CH);  // spatial rows per component (B*H*W)
    const int rowsPerBlock = (S + RBLOCKS - 1) / RBLOCKS;

    k_reduce<<<RBLOCKS, 256>>>(x, S, rowsPerBlock);
    k_stats<<<1, CH>>>(gamma, beta, S);
    k_apply<<<ABLOCKS, 256>>>(x, out, S);
}